// round 12
// baseline (speedup 1.0000x reference)
#include <cuda_runtime.h>
#include <cstddef>

// Problem constants (from reference setup_inputs)
#define B_      64
#define S_      2048
#define D_      768
#define D4_     192          // D_/4 float4s per row
#define POOL_   32
#define L_      8
#define TOPK_   4
#define NTILE_  16           // S_ / SBLK_
#define SBLK_   128
#define PREFIX_ 41           // L_ + TOPK_*L_ + 1
#define OUTROWS_ 2089        // PREFIX_ + S_

// Scratch:
//  g_pdot[b][tile][p] : partial dot of tile's seq-sum with e_keys[p]
//  g_rk[b][p]         : rsqrt(|k_p|^2 + eps), written by tile-0 block of b
//  g_count[b]         : arrival counter; never reset — each replay adds
//                       exactly NTILE_ per batch, so (old+1)%16==0 marks the
//                       last arrival on every graph replay.
__device__ float    g_pdot[B_ * NTILE_ * POOL_];
__device__ float    g_rk[B_ * POOL_];
__device__ unsigned g_count[B_];

// ---------------------------------------------------------------------------
// Single fused kernel. grid = (NTILE_+1, B_), block = 768.
//  - tile blocks 0..15: copy x tile -> out rows [41+s0, 41+s0+128), reduce
//    tile seq-sum in smem, compute 32 partial dots vs e_keys (overlapped with
//    the HBM-bound copy; fma pipe is idle), fan-in via per-batch counter.
//    The LAST arriving block of each batch sums the 16x32 partial dots,
//    normalizes, takes the stable top-4 (== lax.top_k order), and writes the
//    32 selected e-prompt rows. Tail work is O(POOL), not O(D).
//  - tile block 16: writes the selection-independent prefix rows
//    (g_prompts[task_id] x8, cls x1), overlapped with the copy.
// ---------------------------------------------------------------------------
__global__ __launch_bounds__(768, 2)
void fused_kernel(const float4* __restrict__ x4,
                  float4* __restrict__ out4,
                  float* __restrict__ pdot,
                  float* __restrict__ rk,
                  unsigned* __restrict__ count,
                  const float4* __restrict__ g4,
                  const float4* __restrict__ e4,
                  const float*  __restrict__ e_keys,
                  const float4* __restrict__ c4,
                  const int* __restrict__ task_id)
{
    const int tile = blockIdx.x;
    const int b    = blockIdx.y;
    const int tid  = threadIdx.x;

    if (tile == NTILE_) {
        // static prefix rows: g_prompts[task_id] (rows 0..7) and cls (row 40)
        const int t_id = task_id[0];
        const float4* gsrc = g4 + (size_t)t_id * L_ * D4_;
        float4* o = out4 + (size_t)b * OUTROWS_ * D4_;
        for (int i = tid; i < (L_ + 1) * D4_; i += 768) {
            const int row = i / D4_;
            const int c   = i % D4_;
            float4 v = (row < L_) ? gsrc[row * D4_ + c] : c4[c];
            const int orow = (row < L_) ? row : (PREFIX_ - 1);
            o[(size_t)orow * D4_ + c] = v;
        }
        return;
    }

    const int r = tid / D4_;   // 0..3
    const int c = tid % D4_;   // 0..191

    const int s0 = tile * SBLK_;
    const float4* src = x4  + ((size_t)b * S_ + s0) * D4_ + c;
    float4*       dst = out4 + ((size_t)b * OUTROWS_ + PREFIX_ + s0) * D4_ + c;

    float4 acc = make_float4(0.f, 0.f, 0.f, 0.f);
    #pragma unroll 4
    for (int s = r; s < SBLK_; s += 4) {
        float4 v = src[(size_t)s * D4_];
        dst[(size_t)s * D4_] = v;
        acc.x += v.x; acc.y += v.y; acc.z += v.z; acc.w += v.w;
    }

    __shared__ float4 red[768];
    __shared__ float  ts[D_];          // this tile's 768-dim seq-sum
    red[tid] = acc;
    __syncthreads();

    if (r == 0) {
        float4 a0 = red[c];
        float4 a1 = red[D4_ + c];
        float4 a2 = red[2 * D4_ + c];
        float4 a3 = red[3 * D4_ + c];
        float4 s;
        s.x = (a0.x + a1.x) + (a2.x + a3.x);
        s.y = (a0.y + a1.y) + (a2.y + a3.y);
        s.z = (a0.z + a1.z) + (a2.z + a3.z);
        s.w = (a0.w + a1.w) + (a2.w + a3.w);
        ((float4*)ts)[c] = s;
    }
    __syncthreads();

    // partial dots vs e_keys: 24 warps cover 32 pools (warps 0..7 take two)
    const int warp = tid >> 5, lane = tid & 31;
    for (int p = warp; p < POOL_; p += 24) {
        const float* k = e_keys + (size_t)p * D_;
        float dot = 0.f;
        #pragma unroll 4
        for (int d = lane; d < D_; d += 32) dot += ts[d] * k[d];
        #pragma unroll
        for (int off = 16; off; off >>= 1)
            dot += __shfl_xor_sync(0xffffffffu, dot, off);
        if (lane == 0) pdot[((size_t)b * NTILE_ + tile) * POOL_ + p] = dot;
    }

    // tile-0 block also publishes the key norms (release-ordered below)
    if (tile == 0) {
        for (int p = warp; p < POOL_; p += 24) {
            const float* k = e_keys + (size_t)p * D_;
            float kk = 0.f;
            #pragma unroll 4
            for (int d = lane; d < D_; d += 32) { float kv = k[d]; kk += kv * kv; }
            #pragma unroll
            for (int off = 16; off; off >>= 1)
                kk += __shfl_xor_sync(0xffffffffu, kk, off);
            if (lane == 0) rk[b * POOL_ + p] = rsqrtf(kk + 1e-12f);
        }
    }

    // ---- fan-in
    __syncthreads();
    __threadfence();                       // publish pdot/rk writes (all threads)
    __shared__ unsigned is_last;
    if (tid == 0) {
        unsigned old = atomicAdd(&count[b], 1u);
        is_last = (((old + 1u) & (NTILE_ - 1u)) == 0u) ? 1u : 0u;
    }
    __syncthreads();
    if (!is_last) return;
    __threadfence();                       // acquire other blocks' writes

    // sum partial dots, normalize (ranking-equivalent to reference)
    __shared__ float sim[POOL_];
    __shared__ int   sel[TOPK_];
    if (tid < POOL_) {
        const float* pd = pdot + (size_t)b * NTILE_ * POOL_ + tid;
        float s = 0.f;
        #pragma unroll
        for (int t = 0; t < NTILE_; t++) s += pd[t * POOL_];
        sim[tid] = s * rk[b * POOL_ + tid];
    }
    __syncthreads();

    // stable top-4 (strict >, first occurrence wins == lax.top_k)
    if (tid == 0) {
        unsigned used = 0;
        #pragma unroll
        for (int kI = 0; kI < TOPK_; kI++) {
            int best = 0; float bv = -3.4e38f;
            for (int p = 0; p < POOL_; p++) {
                if (used & (1u << p)) continue;
                if (sim[p] > bv) { bv = sim[p]; best = p; }
            }
            used |= (1u << best);
            sel[kI] = best;
        }
    }
    __syncthreads();

    // write the 32 selected e-prompt rows (rows 8..39): 6144 f4, 8 iters
    float4* o = out4 + (size_t)b * OUTROWS_ * D4_;
    for (int i = tid; i < TOPK_ * L_ * D4_; i += 768) {
        const int row = i / D4_;       // 0..31
        const int cc  = i % D4_;
        const int j   = row >> 3;      // selected block 0..3
        const int rr  = row & 7;       // row within block
        float4 v = e4[((size_t)sel[j] * L_ + rr) * D4_ + cc];
        o[(size_t)(L_ + row) * D4_ + cc] = v;
    }
}

// ---------------------------------------------------------------------------
extern "C" void kernel_launch(void* const* d_in, const int* in_sizes, int n_in,
                              void* d_out, int out_size)
{
    const float* x         = (const float*)d_in[0];
    const float* g_prompts = (const float*)d_in[1];
    const float* e_prompts = (const float*)d_in[2];
    const float* e_keys    = (const float*)d_in[3];
    const float* cls_token = (const float*)d_in[4];
    const int*   task_id   = (const int*)  d_in[5];
    float* out = (float*)d_out;

    float* pdot;
    cudaGetSymbolAddress((void**)&pdot, g_pdot);
    float* rk;
    cudaGetSymbolAddress((void**)&rk, g_rk);
    unsigned* cnt;
    cudaGetSymbolAddress((void**)&cnt, g_count);

    dim3 gridA(NTILE_ + 1, B_);
    fused_kernel<<<gridA, 768>>>((const float4*)x,
                                 (float4*)out,
                                 pdot, rk, cnt,
                                 (const float4*)g_prompts,
                                 (const float4*)e_prompts,
                                 e_keys,
                                 (const float4*)cls_token,
                                 task_id);
}

// round 16
// speedup vs baseline: 1.0572x; 1.0572x over previous
#include <cuda_runtime.h>
#include <cstddef>

// Problem constants (from reference setup_inputs)
#define B_      64
#define S_      2048
#define D_      768
#define D4_     192          // D_/4 float4s per row
#define POOL_   32
#define L_      8
#define TOPK_   4
#define NTILE_  16           // S_ / SBLK_
#define SBLK_   128
#define PREFIX_ 41           // L_ + TOPK_*L_ + 1
#define OUTROWS_ 2089        // PREFIX_ + S_

// Scratch: per-(batch, tile) partial sums of x over seq, per-batch top-4.
__device__ float g_partial[B_ * NTILE_ * D_];
__device__ int   g_sel[B_ * TOPK_];

// ---------------------------------------------------------------------------
// Kernel A (UNCHANGED from R7 — measured 118us @ 81.4% DRAM, at roofline).
// Copy x -> out rows [41, 2089) while accumulating per-tile seq-sums.
// Extra block column (tile==16) writes the static prefix rows overlapped.
// ---------------------------------------------------------------------------
__global__ __launch_bounds__(768, 2)
void copy_reduce_kernel(const float4* __restrict__ x4,
                        float4* __restrict__ out4,
                        float4* __restrict__ part4,
                        const float4* __restrict__ g4,
                        const float4* __restrict__ c4,
                        const int* __restrict__ task_id)
{
    const int tile = blockIdx.x;
    const int b    = blockIdx.y;
    const int tid  = threadIdx.x;

    if (tile == NTILE_) {
        const int t_id = task_id[0];
        const float4* gsrc = g4 + (size_t)t_id * L_ * D4_;
        float4* o = out4 + (size_t)b * OUTROWS_ * D4_;
        for (int i = tid; i < (L_ + 1) * D4_; i += 768) {
            const int row = i / D4_;
            const int c   = i % D4_;
            float4 v = (row < L_) ? gsrc[row * D4_ + c] : c4[c];
            const int orow = (row < L_) ? row : (PREFIX_ - 1);
            o[(size_t)orow * D4_ + c] = v;
        }
        return;
    }

    const int r = tid / D4_;   // 0..3
    const int c = tid % D4_;   // 0..191

    const int s0 = tile * SBLK_;
    const float4* src = x4  + ((size_t)b * S_ + s0) * D4_ + c;
    float4*       dst = out4 + ((size_t)b * OUTROWS_ + PREFIX_ + s0) * D4_ + c;

    float4 acc = make_float4(0.f, 0.f, 0.f, 0.f);
    #pragma unroll 4
    for (int s = r; s < SBLK_; s += 4) {
        float4 v = src[(size_t)s * D4_];
        dst[(size_t)s * D4_] = v;
        acc.x += v.x; acc.y += v.y; acc.z += v.z; acc.w += v.w;
    }

    __shared__ float4 red[768];
    red[tid] = acc;
    __syncthreads();

    if (r == 0) {
        float4 a0 = red[c];
        float4 a1 = red[D4_ + c];
        float4 a2 = red[2 * D4_ + c];
        float4 a3 = red[3 * D4_ + c];
        float4 s;
        s.x = (a0.x + a1.x) + (a2.x + a3.x);
        s.y = (a0.y + a1.y) + (a2.y + a3.y);
        s.z = (a0.z + a1.z) + (a2.z + a3.z);
        s.w = (a0.w + a1.w) + (a2.w + a3.w);
        part4[((size_t)b * NTILE_ + tile) * D4_ + c] = s;
    }
}

// ---------------------------------------------------------------------------
// Kernel B1: selection, 64 blocks x 768 threads (was 256 — latency chains
// scale ~1/threads here).
//   1. q-reduce: one dim per thread, 16 fully-unrolled strided L2 loads.
//   2. sim[p] = dot(q,k_p) * rsqrt(|k_p|^2+eps): 24 warps over 32 pools
//      (warps 0..7 take two pools), 24 loads/lane/pool.
//   3. stable top-4 (strict >, first occurrence wins == lax.top_k).
// ---------------------------------------------------------------------------
__global__ __launch_bounds__(768)
void select_kernel(const float* __restrict__ e_keys,
                   const float* __restrict__ part,
                   int* __restrict__ sel_out)
{
    const int b   = blockIdx.x;
    const int tid = threadIdx.x;

    __shared__ float q[D_];
    __shared__ float sim[POOL_];

    // 1. q-reduce: thread tid owns dim tid
    {
        const float* p = part + (size_t)b * NTILE_ * D_ + tid;
        float s = 0.f;
        #pragma unroll
        for (int t = 0; t < NTILE_; t++) s += p[(size_t)t * D_];
        q[tid] = s;
    }
    __syncthreads();

    // 2. dots
    const int warp = tid >> 5, lane = tid & 31;
    for (int p = warp; p < POOL_; p += 24) {
        const float* k = e_keys + (size_t)p * D_;
        float dot = 0.f, kk = 0.f;
        #pragma unroll
        for (int d = lane; d < D_; d += 32) {
            float kv = __ldg(&k[d]);
            dot += q[d] * kv;
            kk  += kv * kv;
        }
        #pragma unroll
        for (int off = 16; off; off >>= 1) {
            dot += __shfl_xor_sync(0xffffffffu, dot, off);
            kk  += __shfl_xor_sync(0xffffffffu, kk,  off);
        }
        if (lane == 0) sim[p] = dot * rsqrtf(kk + 1e-12f);
    }
    __syncthreads();

    // 3. stable top-4
    if (tid == 0) {
        unsigned used = 0;
        #pragma unroll
        for (int kI = 0; kI < TOPK_; kI++) {
            int best = 0; float bv = -3.4e38f;
            #pragma unroll
            for (int p = 0; p < POOL_; p++) {
                if (used & (1u << p)) continue;
                if (sim[p] > bv) { bv = sim[p]; best = p; }
            }
            used |= (1u << best);
            sel_out[b * TOPK_ + kI] = best;
        }
    }
}

// ---------------------------------------------------------------------------
// Kernel B2: write selected e-prompt rows. grid (32, 64), 192 threads:
// one block per (e-row, batch), one float4 per thread. ~2us.
// ---------------------------------------------------------------------------
__global__ __launch_bounds__(192)
void eprompt_write_kernel(const float4* __restrict__ e4,
                          const int* __restrict__ sel,
                          float4* __restrict__ out4)
{
    const int row = blockIdx.x;           // 0..31 within e-section
    const int b   = blockIdx.y;
    const int c   = threadIdx.x;          // 0..191
    const int j   = row >> 3;             // selected block index 0..3
    const int rr  = row & 7;              // row within 8-row block
    const int p   = sel[b * TOPK_ + j];

    float4 v = e4[((size_t)p * L_ + rr) * D4_ + c];
    out4[((size_t)b * OUTROWS_ + L_ + row) * D4_ + c] = v;
}

// ---------------------------------------------------------------------------
extern "C" void kernel_launch(void* const* d_in, const int* in_sizes, int n_in,
                              void* d_out, int out_size)
{
    const float* x         = (const float*)d_in[0];
    const float* g_prompts = (const float*)d_in[1];
    const float* e_prompts = (const float*)d_in[2];
    const float* e_keys    = (const float*)d_in[3];
    const float* cls_token = (const float*)d_in[4];
    const int*   task_id   = (const int*)  d_in[5];
    float* out = (float*)d_out;

    float* part;
    cudaGetSymbolAddress((void**)&part, g_partial);
    int* sel;
    cudaGetSymbolAddress((void**)&sel, g_sel);

    dim3 gridA(NTILE_ + 1, B_);
    copy_reduce_kernel<<<gridA, 768>>>((const float4*)x,
                                       (float4*)out,
                                       (float4*)part,
                                       (const float4*)g_prompts,
                                       (const float4*)cls_token,
                                       task_id);

    select_kernel<<<B_, 768>>>(e_keys, part, sel);

    dim3 gridB2(TOPK_ * L_, B_);
    eprompt_write_kernel<<<gridB2, 192>>>((const float4*)e_prompts, sel,
                                          (float4*)out);
}